// round 4
// baseline (speedup 1.0000x reference)
#include <cuda_runtime.h>
#include <math.h>

// Problem sizes (fixed by the reference)
#define NB    8192
#define NPTS  16384              // combined base+target
#define TILE  256
#define NTILES (NPTS / TILE)     // 64
#define NPAIRS (NTILES * (NTILES + 1) / 2)   // 2080
#define K1_BLOCK 256
#define K1_GRID  (NPTS / K1_BLOCK)           // 64 (blocks 0..31 base, 32..63 target)

struct MmdConsts {
    float sq;            // sqrt(inv * log2e): coordinate prescale
    float sx, sy;        // exp(log_scale)
    float mxb, myb;      // base weighted mean (scaled coords)
    float mxt, myt;      // target weighted mean
    float invUb, invUt;  // 1 / sum of unnormalized weights
    float gate;          // descriptor gate
};

// Scratch (static __device__ globals: no allocations allowed)
__device__ float     g_u[NPTS];          // unnormalized node weights
__device__ float     g_bp[K1_GRID * 3];  // per-block partials (U, Sx, Sy)
__device__ float4    g_pts[NPTS];        // (qx, qy, B=-|q|^2, signed weight s)
__device__ float     g_partial[NPAIRS];  // per-CTA MMD partials
__device__ MmdConsts g_c;

__device__ __forceinline__ float ex2f(float x) {
    float y;
    asm("ex2.approx.ftz.f32 %0, %1;" : "=f"(y) : "f"(x));
    return y;
}

__device__ __forceinline__ float softplusf(float x) {
    // matches jax.nn.softplus = max(x,0) + log1p(exp(-|x|))
    return fmaxf(x, 0.0f) + log1pf(expf(-fabsf(x)));
}

// ---------------------------------------------------------------------------
// K1: per-point unnormalized weight u = softplus(MLP(feat)) + 1e-6,
//     plus deterministic per-block partial sums of (u, u*px, u*py).
// ---------------------------------------------------------------------------
__global__ void k1_weights(const float* __restrict__ bfeat,
                           const float* __restrict__ tfeat,
                           const float* __restrict__ bpos,
                           const float* __restrict__ tpos,
                           const float* __restrict__ w1,
                           const float* __restrict__ b1,
                           const float* __restrict__ w2,
                           const float* __restrict__ b2)
{
    int i = blockIdx.x * blockDim.x + threadIdx.x;
    bool isb = (i < NB);
    const float* feat = isb ? (bfeat + i * 5) : (tfeat + (i - NB) * 5);
    const float* pos  = isb ? (bpos + i * 2)  : (tpos + (i - NB) * 2);

    float f0 = feat[0], f1 = feat[1], f2 = feat[2], f3 = feat[3], f4 = feat[4];
    float logit = __ldg(b2);
#pragma unroll
    for (int j = 0; j < 32; j++) {
        float h = __ldg(b1 + j);
        h = fmaf(f0, __ldg(w1 + 0 * 32 + j), h);
        h = fmaf(f1, __ldg(w1 + 1 * 32 + j), h);
        h = fmaf(f2, __ldg(w1 + 2 * 32 + j), h);
        h = fmaf(f3, __ldg(w1 + 3 * 32 + j), h);
        h = fmaf(f4, __ldg(w1 + 4 * 32 + j), h);
        h = fmaxf(h, 0.0f);
        logit = fmaf(h, __ldg(w2 + j), logit);
    }
    float u = softplusf(logit) + 1e-6f;
    g_u[i] = u;

    __shared__ float sU[K1_BLOCK], sX[K1_BLOCK], sY[K1_BLOCK];
    sU[threadIdx.x] = u;
    sX[threadIdx.x] = u * pos[0];
    sY[threadIdx.x] = u * pos[1];
    __syncthreads();
    for (int s = K1_BLOCK / 2; s > 0; s >>= 1) {
        if (threadIdx.x < s) {
            sU[threadIdx.x] += sU[threadIdx.x + s];
            sX[threadIdx.x] += sX[threadIdx.x + s];
            sY[threadIdx.x] += sY[threadIdx.x + s];
        }
        __syncthreads();
    }
    if (threadIdx.x == 0) {
        g_bp[blockIdx.x * 3 + 0] = sU[0];
        g_bp[blockIdx.x * 3 + 1] = sX[0];
        g_bp[blockIdx.x * 3 + 2] = sY[0];
    }
}

// ---------------------------------------------------------------------------
// K2: single block. Reduce block partials -> cloud totals, compute constants
//     (means, scales, prescale factor) and the descriptor gate.
// ---------------------------------------------------------------------------
__global__ void k2_consts(const float* __restrict__ bdesc,
                          const float* __restrict__ tdesc,
                          const float* __restrict__ g1,
                          const float* __restrict__ gb1,
                          const float* __restrict__ g2,
                          const float* __restrict__ gb2,
                          const float* __restrict__ log_sigma,
                          const float* __restrict__ log_scale)
{
    if (threadIdx.x != 0) return;
    float Ub = 0.f, Sxb = 0.f, Syb = 0.f, Ut = 0.f, Sxt = 0.f, Syt = 0.f;
#pragma unroll
    for (int b = 0; b < 32; b++) {
        Ub  += g_bp[b * 3 + 0];
        Sxb += g_bp[b * 3 + 1];
        Syb += g_bp[b * 3 + 2];
    }
#pragma unroll
    for (int b = 32; b < 64; b++) {
        Ut  += g_bp[b * 3 + 0];
        Sxt += g_bp[b * 3 + 1];
        Syt += g_bp[b * 3 + 2];
    }
    float sx = expf(log_scale[0]);
    float sy = expf(log_scale[1]);
    float sigma = expf(log_sigma[0]);
    float inv = 1.0f / (2.0f * sigma * sigma);
    float cc = inv * 1.44269504088896340736f;  // inv * log2(e)

    g_c.sq = sqrtf(cc);
    g_c.sx = sx; g_c.sy = sy;
    g_c.mxb = sx * Sxb / Ub;  g_c.myb = sy * Syb / Ub;
    g_c.mxt = sx * Sxt / Ut;  g_c.myt = sy * Syt / Ut;
    g_c.invUb = 1.0f / Ub;    g_c.invUt = 1.0f / Ut;

    // descriptor gate: softplus(relu(|bd-td| @ g1 + gb1) @ g2 + gb2) + 1e-6
    float d0 = fabsf(bdesc[0] - tdesc[0]);
    float d1 = fabsf(bdesc[1] - tdesc[1]);
    float d2 = fabsf(bdesc[2] - tdesc[2]);
    float d3 = fabsf(bdesc[3] - tdesc[3]);
    float logit = gb2[0];
#pragma unroll
    for (int j = 0; j < 32; j++) {
        float h = gb1[j];
        h = fmaf(d0, g1[0 * 32 + j], h);
        h = fmaf(d1, g1[1 * 32 + j], h);
        h = fmaf(d2, g1[2 * 32 + j], h);
        h = fmaf(d3, g1[3 * 32 + j], h);
        h = fmaxf(h, 0.0f);
        logit = fmaf(h, g2[j], logit);
    }
    g_c.gate = softplusf(logit) + 1e-6f;
}

// ---------------------------------------------------------------------------
// K3: prepare per-point (qx, qy, B, s). q = (pos*scale - mean)*sq,
//     B = -|q|^2, s = +u/Ub (base) or -u/Ut (target).
// ---------------------------------------------------------------------------
__global__ void k3_prep(const float* __restrict__ bpos,
                        const float* __restrict__ tpos)
{
    int i = blockIdx.x * blockDim.x + threadIdx.x;
    MmdConsts c = g_c;
    bool isb = (i < NB);
    const float* pos = isb ? (bpos + i * 2) : (tpos + (i - NB) * 2);
    float qx = (pos[0] * c.sx - (isb ? c.mxb : c.mxt)) * c.sq;
    float qy = (pos[1] * c.sy - (isb ? c.myb : c.myt)) * c.sq;
    float B  = -(fmaf(qx, qx, qy * qy));
    float s  = g_u[i] * (isb ? c.invUb : -c.invUt);
    g_pts[i] = make_float4(qx, qy, B, s);
}

// ---------------------------------------------------------------------------
// K4: symmetric tiled MMD. CTA -> tile pair (bi <= bj); off-diagonal doubled.
//     arg = Bi + Bj + 2*qi.qj (in log2 units)  =>  k = 2^arg.
//     Inner loop per pair: 1 LDS.128 (broadcast) + FADD + 2 FFMA + EX2 + FFMA.
// ---------------------------------------------------------------------------
__global__ void __launch_bounds__(TILE) k4_mmd()
{
    // decode linear CTA index -> (bi, bj), bi <= bj
    int rem = blockIdx.x;
    int bi = 0;
    while (rem >= NTILES - bi) { rem -= NTILES - bi; bi++; }
    int bj = bi + rem;

    __shared__ float4 sj[TILE];
    sj[threadIdx.x] = g_pts[bj * TILE + threadIdx.x];
    __syncthreads();

    float4 pi = g_pts[bi * TILE + threadIdx.x];
    float xi2 = 2.0f * pi.x;
    float yi2 = 2.0f * pi.y;
    float Bi  = pi.z;
    float si  = pi.w;

    float acc = 0.0f;
#pragma unroll 8
    for (int j = 0; j < TILE; j++) {
        float4 pj = sj[j];
        float a = Bi + pj.z;
        a = fmaf(yi2, pj.y, a);
        a = fmaf(xi2, pj.x, a);
        float k = ex2f(a);
        acc = fmaf(pj.w, k, acc);
    }
    float val = si * acc;

    __shared__ float red[TILE];
    red[threadIdx.x] = val;
    __syncthreads();
    for (int s = TILE / 2; s > 0; s >>= 1) {
        if (threadIdx.x < s) red[threadIdx.x] += red[threadIdx.x + s];
        __syncthreads();
    }
    if (threadIdx.x == 0)
        g_partial[blockIdx.x] = (bi == bj) ? red[0] : 2.0f * red[0];
}

// ---------------------------------------------------------------------------
// K5: final deterministic reduce (double), apply gate + bias.
// ---------------------------------------------------------------------------
__global__ void k5_final(const float* __restrict__ bias, float* __restrict__ out)
{
    __shared__ double red[256];
    double a = 0.0;
    for (int i = threadIdx.x; i < NPAIRS; i += 256) a += (double)g_partial[i];
    red[threadIdx.x] = a;
    __syncthreads();
    for (int s = 128; s > 0; s >>= 1) {
        if (threadIdx.x < s) red[threadIdx.x] += red[threadIdx.x + s];
        __syncthreads();
    }
    if (threadIdx.x == 0)
        out[0] = (float)(red[0] * (double)g_c.gate + (double)bias[0]);
}

// ---------------------------------------------------------------------------
extern "C" void kernel_launch(void* const* d_in, const int* in_sizes, int n_in,
                              void* d_out, int out_size)
{
    const float* base_pos    = (const float*)d_in[0];
    const float* base_feat   = (const float*)d_in[1];
    const float* base_desc   = (const float*)d_in[2];
    const float* target_pos  = (const float*)d_in[3];
    const float* target_feat = (const float*)d_in[4];
    const float* target_desc = (const float*)d_in[5];
    const float* w1  = (const float*)d_in[6];
    const float* b1  = (const float*)d_in[7];
    const float* w2  = (const float*)d_in[8];
    const float* b2  = (const float*)d_in[9];
    const float* g1  = (const float*)d_in[10];
    const float* gb1 = (const float*)d_in[11];
    const float* g2  = (const float*)d_in[12];
    const float* gb2 = (const float*)d_in[13];
    const float* log_sigma = (const float*)d_in[14];
    const float* log_scale = (const float*)d_in[15];
    const float* bias      = (const float*)d_in[16];
    float* out = (float*)d_out;

    k1_weights<<<K1_GRID, K1_BLOCK>>>(base_feat, target_feat, base_pos, target_pos,
                                      w1, b1, w2, b2);
    k2_consts<<<1, 32>>>(base_desc, target_desc, g1, gb1, g2, gb2,
                         log_sigma, log_scale);
    k3_prep<<<NPTS / 256, 256>>>(base_pos, target_pos);
    k4_mmd<<<NPAIRS, TILE>>>();
    k5_final<<<1, 256>>>(bias, out);
}